// round 8
// baseline (speedup 1.0000x reference)
#include <cuda_runtime.h>
#include <math.h>
#include <stdint.h>

#define BB 4
#define LL 2048
#define LQ 1024
#define DM 512
#define DIN 1024
#define DSTATE 64
#define NH 16
#define HD 64
#define DXBC 1152
#define ZXW 2176      // z + xBC columns kept in g_zx (row stride)
#define WIN_LD 2192   // full in_proj width (z + xBC + dt)

// ---------------- scratch (device globals; allocation-free) ----------------
__device__ float g_u[2][BB*LL*DM];        // rmsnormed inputs (fp32, for dt path)
__device__ float g_u32[2][BB*LL*DM];      // rmsnormed inputs (tf32-rounded, GEMM A)
__device__ float g_zx[2][BB*LL*ZXW];      // in_proj outputs (z + xBC)
__device__ float g_xbc[2][BB*LL*DXBC];    // conv+silu outputs
__device__ float g_dt[2][BB*LL*NH];
__device__ float g_dA[2][BB*LL*NH];
__device__ float g_y[2][BB*LL*DIN];       // scan outputs (+D*x)
__device__ float g_nrm[2][BB*LQ*DIN];     // gated rmsnorm (tf32-rounded)
__device__ float g_fs[BB*LQ*DM];          // factual pre-out-proj (tf32-rounded)
__device__ float g_win32[2][DM*ZXW];      // tf32 weights
__device__ float g_wout32[2][DIN*DM];
__device__ float g_wo32[DM*DM];

// ---------------- helpers ----------------
__device__ __forceinline__ float silu(float x) { return x / (1.f + expf(-x)); }

__device__ __forceinline__ uint32_t f2tf32(float x) {
    uint32_t r;
    asm("cvt.rna.tf32.f32 %0, %1;" : "=r"(r) : "f"(x));
    return r;
}
__device__ __forceinline__ float tf32r(float x) { return __uint_as_float(f2tf32(x)); }

__device__ __forceinline__ void mma_tf32(float* c, const uint32_t* a, const uint32_t* b) {
    asm volatile("mma.sync.aligned.m16n8k8.row.col.f32.tf32.tf32.f32 "
        "{%0,%1,%2,%3}, {%4,%5,%6,%7}, {%8,%9}, {%0,%1,%2,%3};"
        : "+f"(c[0]), "+f"(c[1]), "+f"(c[2]), "+f"(c[3])
        : "r"(a[0]), "r"(a[1]), "r"(a[2]), "r"(a[3]), "r"(b[0]), "r"(b[1]));
}

__device__ __forceinline__ void cpa16(float* dst, const float* src) {
    uint32_t d = (uint32_t)__cvta_generic_to_shared(dst);
    asm volatile("cp.async.cg.shared.global [%0], [%1], 16;" :: "r"(d), "l"(src));
}
__device__ __forceinline__ void cpa_commit() { asm volatile("cp.async.commit_group;"); }
template<int N> __device__ __forceinline__ void cpa_wait() {
    asm volatile("cp.async.wait_group %0;" :: "n"(N));
}

// ---------------- 1) input rmsnorm (concat + optional flip) ----------------
__global__ void prep_norm(const float* __restrict__ q, const float* __restrict__ kv,
                          const float* __restrict__ fw, const float* __restrict__ cw)
{
    int row = blockIdx.x;            // 2 * 4 * 2048 rows
    int br  = row >> 13;
    int r   = row & 8191;
    int b   = r >> 11;
    int l   = r & 2047;
    const float* src;
    if (l < LQ) {
        int li = (br == 0) ? l : (LQ - 1 - l);
        src = kv + (b * LQ + li) * DM;
    } else {
        src = q + (b * LQ + (l - LQ)) * DM;
    }
    const float* w = br ? cw : fw;

    int t = threadIdx.x;             // 128
    float v[4];
    float ss = 0.f;
#pragma unroll
    for (int i = 0; i < 4; i++) { v[i] = src[t + i * 128]; ss += v[i] * v[i]; }

    __shared__ float red[4];
#pragma unroll
    for (int o = 16; o > 0; o >>= 1) ss += __shfl_xor_sync(0xffffffffu, ss, o);
    if ((t & 31) == 0) red[t >> 5] = ss;
    __syncthreads();
    float total = red[0] + red[1] + red[2] + red[3];
    float scale = rsqrtf(total / (float)DM + 1e-5f);

    float* dst   = g_u[br]   + (b * LL + l) * DM;
    float* dst32 = g_u32[br] + (b * LL + l) * DM;
#pragma unroll
    for (int i = 0; i < 4; i++) {
        int idx = t + i * 128;
        float val = v[i] * scale * w[idx];
        dst[idx] = val;
        dst32[idx] = tf32r(val);
    }
}

// ---------------- dt GEMM (fp32) + softplus + dA (both branches) -----------
__global__ void __launch_bounds__(256) dt_gemm(
    const float* __restrict__ fWin, const float* __restrict__ cWin,
    const float* __restrict__ fdtb, const float* __restrict__ cdtb,
    const float* __restrict__ fAl,  const float* __restrict__ cAl)
{
    int br = blockIdx.y;
    const float* Win = br ? cWin : fWin;
    const float* dtb = br ? cdtb : fdtb;
    const float* Alog = br ? cAl : fAl;
    const float* u = g_u[br];

    __shared__ float Ws[512][16];
    int tid = threadIdx.x;
    for (int i = tid; i < 512 * 16; i += 256) {
        int k = i >> 4, h = i & 15;
        Ws[k][h] = Win[k * WIN_LD + ZXW + h];
    }
    __syncthreads();

    int rib = tid >> 4;
    int h   = tid & 15;
    int row = blockIdx.x * 16 + rib;
    const float* arow = u + row * DM;

    float a0 = 0.f, a1 = 0.f, a2 = 0.f, a3 = 0.f;
#pragma unroll 4
    for (int k = 0; k < 512; k += 4) {
        a0 += arow[k]     * Ws[k][h];
        a1 += arow[k + 1] * Ws[k + 1][h];
        a2 += arow[k + 2] * Ws[k + 2][h];
        a3 += arow[k + 3] * Ws[k + 3][h];
    }
    float acc = dtb[h] + ((a0 + a1) + (a2 + a3));

    float dt = acc > 20.f ? acc : log1pf(expf(acc));
    int idx = row * NH + h;
    g_dt[br][idx] = dt;
    g_dA[br][idx] = expf(-expf(Alog[h]) * dt);
}

// ---------------- weight tf32 conversion (single launch, 5 regions) --------
__global__ void cvt_all(const float* __restrict__ fWin, const float* __restrict__ cWin,
                        const float* __restrict__ fWout, const float* __restrict__ cWout,
                        const float* __restrict__ oW)
{
    int reg = blockIdx.y;
    int i = blockIdx.x * 256 + threadIdx.x;
    if (reg < 2) {
        if (i >= DM * ZXW) return;
        const float* s = reg ? cWin : fWin;
        float* d = g_win32[reg];
        int r = i / ZXW, c = i - r * ZXW;
        d[i] = tf32r(s[r * WIN_LD + c]);
    } else if (reg < 4) {
        if (i >= DIN * DM) return;
        const float* s = (reg == 2) ? fWout : cWout;
        g_wout32[reg - 2][i] = tf32r(s[i]);
    } else {
        if (i >= DM * DM) return;
        g_wo32[i] = tf32r(oW[i]);
    }
}

// ---------------- TF32 GEMM: 256x128x32 tile, 8 warps (64x64), 3-stage -----
#define AS_LD 36
#define BS_LD 136
#define A_STG (256 * AS_LD)    // 9216 floats
#define B_STG (32 * BS_LD)     // 4352 floats
#define B_OFF (3 * A_STG)
#define GEMM_SMEM ((3 * (A_STG + B_STG)) * 4)   // 162816 B

__global__ void __launch_bounds__(256) gemm_tf32(
    const float* __restrict__ A0, const float* __restrict__ A1,
    const float* __restrict__ B0, const float* __restrict__ B1,
    float* __restrict__ C0, float* __restrict__ C1,
    const float* __restrict__ bias,
    int M, int N, int K, int lda, int ldb, int ldc, int roundMask)
{
    extern __shared__ float sm[];
    int z = blockIdx.z;
    const float* A = z ? A1 : A0;
    const float* B = z ? B1 : B0;
    float* C = z ? C1 : C0;
    bool rnd = (roundMask >> z) & 1;

    int tid = threadIdx.x;
    int bm = blockIdx.y * 256, bn = blockIdx.x * 128;

    int w = tid >> 5;
    int lane = tid & 31;
    int g = lane >> 2, cq = lane & 3;
    int mw = (w & 3) * 64;
    int nw = (w >> 2) * 64;

    // loads: A row per thread (8 quads), B 4 quads per thread
    const float* Ag = A + (bm + tid) * lda;
    int b_r = tid >> 3, b_cc = (tid & 7) * 16;
    const float* Bg = B + b_r * ldb + bn + b_cc;

    int nk = K >> 5;

#pragma unroll
    for (int st = 0; st < 2; st++) {
        float* As = sm + st * A_STG;
        float* Bs = sm + B_OFF + st * B_STG;
#pragma unroll
        for (int q = 0; q < 8; q++)
            cpa16(&As[tid * AS_LD + q * 4], Ag + st * 32 + q * 4);
#pragma unroll
        for (int q = 0; q < 4; q++)
            cpa16(&Bs[b_r * BS_LD + b_cc + q * 4], Bg + st * 32 * ldb + q * 4);
        cpa_commit();
    }

    float acc[4][8][4];
#pragma unroll
    for (int i = 0; i < 4; i++)
#pragma unroll
        for (int j = 0; j < 8; j++)
#pragma unroll
            for (int x = 0; x < 4; x++) acc[i][j][x] = 0.f;

    for (int kt = 0; kt < nk; kt++) {
        if (kt + 1 < nk) cpa_wait<1>(); else cpa_wait<0>();
        __syncthreads();

        if (kt + 2 < nk) {
            int st = (kt + 2) % 3;
            float* As = sm + st * A_STG;
            float* Bs = sm + B_OFF + st * B_STG;
            int k0 = (kt + 2) * 32;
#pragma unroll
            for (int q = 0; q < 8; q++)
                cpa16(&As[tid * AS_LD + q * 4], Ag + k0 + q * 4);
#pragma unroll
            for (int q = 0; q < 4; q++)
                cpa16(&Bs[b_r * BS_LD + b_cc + q * 4], Bg + k0 * ldb + q * 4);
            cpa_commit();
        }

        const float* As = sm + (kt % 3) * A_STG;
        const float* Bs = sm + B_OFF + (kt % 3) * B_STG;
#pragma unroll
        for (int ks = 0; ks < 4; ks++) {
            int k0 = ks * 8;
            uint32_t af[4][4], bf[8][2];
#pragma unroll
            for (int i = 0; i < 4; i++) {
                int m = mw + i * 16 + g;
                af[i][0] = __float_as_uint(As[m * AS_LD + k0 + cq]);
                af[i][1] = __float_as_uint(As[(m + 8) * AS_LD + k0 + cq]);
                af[i][2] = __float_as_uint(As[m * AS_LD + k0 + cq + 4]);
                af[i][3] = __float_as_uint(As[(m + 8) * AS_LD + k0 + cq + 4]);
            }
#pragma unroll
            for (int j = 0; j < 8; j++) {
                int n = nw + j * 8 + g;
                bf[j][0] = __float_as_uint(Bs[(k0 + cq) * BS_LD + n]);
                bf[j][1] = __float_as_uint(Bs[(k0 + cq + 4) * BS_LD + n]);
            }
#pragma unroll
            for (int i = 0; i < 4; i++)
#pragma unroll
                for (int j = 0; j < 8; j++)
                    mma_tf32(acc[i][j], af[i], bf[j]);
        }
    }

    // epilogue
#pragma unroll
    for (int i = 0; i < 4; i++) {
        int m0 = bm + mw + i * 16 + g;
#pragma unroll
        for (int j = 0; j < 8; j++) {
            int n = bn + nw + j * 8 + 2 * cq;
            float b0 = 0.f, b1 = 0.f;
            if (bias) { b0 = bias[n]; b1 = bias[n + 1]; }
            float v00 = acc[i][j][0] + b0, v01 = acc[i][j][1] + b1;
            float v10 = acc[i][j][2] + b0, v11 = acc[i][j][3] + b1;
            if (rnd) { v00 = tf32r(v00); v01 = tf32r(v01); v10 = tf32r(v10); v11 = tf32r(v11); }
            float2 lo = { v00, v01 }, hi = { v10, v11 };
            *(float2*)&C[m0 * ldc + n] = lo;
            *(float2*)&C[(m0 + 8) * ldc + n] = hi;
        }
    }
}

// ---------------- causal depthwise conv + silu (vectorized, no div) --------
__global__ void __launch_bounds__(288) conv_silu(
    const float* __restrict__ fw, const float* __restrict__ fb,
    const float* __restrict__ cw_, const float* __restrict__ cb)
{
    int br = blockIdx.y;
    const float* w = br ? cw_ : fw;
    const float* bias = br ? cb : fb;
    int row = blockIdx.x;            // BB * LL
    int b = row >> 11;
    int l = row & 2047;
    int c4 = threadIdx.x * 4;        // 288 threads * 4 ch = 1152

    // 16 weights for 4 channels
    float4 w0 = *(const float4*)(w + c4 * 4);
    float4 w1 = *(const float4*)(w + c4 * 4 + 4);
    float4 w2 = *(const float4*)(w + c4 * 4 + 8);
    float4 w3 = *(const float4*)(w + c4 * 4 + 12);
    float4 acc = *(const float4*)(bias + c4);

    const float* zbase = g_zx[br] + (size_t)(b * LL) * ZXW + DIN + c4;
#pragma unroll
    for (int j = 0; j < 4; j++) {
        int ls = l - 3 + j;
        if (ls >= 0) {
            float4 x = *(const float4*)(zbase + (size_t)ls * ZXW);
            acc.x += x.x * ((const float*)&w0)[j];
            acc.y += x.y * ((const float*)&w1)[j];
            acc.z += x.z * ((const float*)&w2)[j];
            acc.w += x.w * ((const float*)&w3)[j];
        }
    }
    float4 outv = { silu(acc.x), silu(acc.y), silu(acc.z), silu(acc.w) };
    *(float4*)(g_xbc[br] + (size_t)row * DXBC + c4) = outv;
}

// ---------------- SSD sequential scan, 8-step chunks, batched shfl ---------
#define CHS 8
__global__ void __launch_bounds__(512) scan_kernel(const float* __restrict__ fD,
                                                   const float* __restrict__ cD)
{
    int blk = blockIdx.x;            // 128 = 2 * 4 * 16
    int br = blk >> 6;
    int r = blk & 63;
    int b = r >> 4;
    int h = r & 15;
    const float* xbc = g_xbc[br];
    const float* dtp = g_dt[br];
    const float* dAp = g_dA[br];
    const float* Dp  = br ? cD : fD;
    float* yp = g_y[br];

    __shared__ float xs[2][CHS][64], bs[2][CHS][64], cs_[2][CHS][64], sc[2][CHS][2];

    int t = threadIdx.x;             // 512
    int p = t >> 3;
    int nb = (t & 7) << 3;
    int step = t >> 6, slot = t & 63;
    float Dh = Dp[h];

    float hreg[8];
#pragma unroll
    for (int j = 0; j < 8; j++) hreg[j] = 0.f;

    int rowbase = b * LL;

    float rx, rb, rc, rs = 0.f;
    {
        const float* base = xbc + (rowbase + step) * DXBC;
        rx = base[h * 64 + slot];
        rb = base[1024 + slot];
        rc = base[1088 + slot];
        if (t < 8)       rs = dtp[(rowbase + t) * NH + h];
        else if (t < 16) rs = dAp[(rowbase + (t - 8)) * NH + h];
    }

    int cur = 0;
    for (int c = 0; c < LL / CHS; c++) {
        xs[cur][step][slot]  = rx;
        bs[cur][step][slot]  = rb;
        cs_[cur][step][slot] = rc;
        if (t < 8)       sc[cur][t][0] = rs;
        else if (t < 16) sc[cur][t - 8][1] = rs;
        __syncthreads();

        if (c + 1 < LL / CHS) {
            int l0n = (c + 1) * CHS;
            const float* base = xbc + (rowbase + l0n + step) * DXBC;
            rx = base[h * 64 + slot];
            rb = base[1024 + slot];
            rc = base[1088 + slot];
            if (t < 8)       rs = dtp[(rowbase + l0n + t) * NH + h];
            else if (t < 16) rs = dAp[(rowbase + l0n + (t - 8)) * NH + h];
        }

        float accv[CHS], yv[CHS];
#pragma unroll
        for (int s = 0; s < CHS; s++) {
            float dtv = sc[cur][s][0], dav = sc[cur][s][1];
            float xv = xs[cur][s][p];
            float dtx = dtv * xv;
            float4 b0 = *(const float4*)&bs[cur][s][nb];
            float4 b1 = *(const float4*)&bs[cur][s][nb + 4];
            float4 c0 = *(const float4*)&cs_[cur][s][nb];
            float4 c1 = *(const float4*)&cs_[cur][s][nb + 4];
            float a;
            hreg[0] = hreg[0] * dav + dtx * b0.x; a  = hreg[0] * c0.x;
            hreg[1] = hreg[1] * dav + dtx * b0.y; a += hreg[1] * c0.y;
            hreg[2] = hreg[2] * dav + dtx * b0.z; a += hreg[2] * c0.z;
            hreg[3] = hreg[3] * dav + dtx * b0.w; a += hreg[3] * c0.w;
            hreg[4] = hreg[4] * dav + dtx * b1.x; a += hreg[4] * c1.x;
            hreg[5] = hreg[5] * dav + dtx * b1.y; a += hreg[5] * c1.y;
            hreg[6] = hreg[6] * dav + dtx * b1.z; a += hreg[6] * c1.z;
            hreg[7] = hreg[7] * dav + dtx * b1.w; a += hreg[7] * c1.w;
            accv[s] = a;
            yv[s] = Dh * xv;
        }
        // batched reduction: 8 independent 3-deep shfl chains
#pragma unroll
        for (int s = 0; s < CHS; s++) accv[s] += __shfl_xor_sync(0xffffffffu, accv[s], 1);
#pragma unroll
        for (int s = 0; s < CHS; s++) accv[s] += __shfl_xor_sync(0xffffffffu, accv[s], 2);
#pragma unroll
        for (int s = 0; s < CHS; s++) accv[s] += __shfl_xor_sync(0xffffffffu, accv[s], 4);

        int l0 = c * CHS;
        if ((t & 7) == 0) {
#pragma unroll
            for (int s = 0; s < CHS; s++)
                yp[(rowbase + l0 + s) * DIN + h * HD + p] = accv[s] + yv[s];
        }
        cur ^= 1;
    }
}

// ---------------- y * silu(z) + rmsnorm (last LQ tokens, tf32 out) ---------
__global__ void yz_norm(const float* __restrict__ fnw, const float* __restrict__ cnw)
{
    int row = blockIdx.x;            // 2 * 4 * 1024
    int br = row >> 12;
    int r = row & 4095;
    int b = r >> 10;
    int lq = r & 1023;
    int l = lq + LQ;
    const float* nw = br ? cnw : fnw;
    const float* yrow = g_y[br] + (b * LL + l) * DIN;
    const float* zrow = g_zx[br] + (b * LL + l) * ZXW;

    int t = threadIdx.x;             // 256
    float v[4];
    float ss = 0.f;
#pragma unroll
    for (int i = 0; i < 4; i++) {
        int idx = t + i * 256;
        float z = zrow[idx];
        float val = yrow[idx] * silu(z);
        v[i] = val;
        ss += val * val;
    }

    __shared__ float red[8];
#pragma unroll
    for (int o = 16; o > 0; o >>= 1) ss += __shfl_xor_sync(0xffffffffu, ss, o);
    if ((t & 31) == 0) red[t >> 5] = ss;
    __syncthreads();
    float total = 0.f;
#pragma unroll
    for (int i = 0; i < 8; i++) total += red[i];
    float scale = rsqrtf(total / (float)DIN + 1e-5f);

    float* dst = g_nrm[br] + ((b << 10) + lq) * DIN;
#pragma unroll
    for (int i = 0; i < 4; i++) {
        int idx = t + i * 256;
        dst[idx] = tf32r(v[i] * scale * nw[idx]);
    }
}

// ---------------- launch ----------------------------------------------------
extern "C" void kernel_launch(void* const* d_in, const int* in_sizes, int n_in,
                              void* d_out, int out_size)
{
    const float* query   = (const float*)d_in[0];
    const float* kv      = (const float*)d_in[1];
    const float* fnorm_w = (const float*)d_in[2];
    const float* cnorm_w = (const float*)d_in[3];
    const float* f_Win   = (const float*)d_in[4];
    const float* f_convw = (const float*)d_in[5];
    const float* f_convb = (const float*)d_in[6];
    const float* f_dtb   = (const float*)d_in[7];
    const float* f_Alog  = (const float*)d_in[8];
    const float* f_D     = (const float*)d_in[9];
    const float* f_normw = (const float*)d_in[10];
    const float* f_Wout  = (const float*)d_in[11];
    const float* c_Win   = (const float*)d_in[12];
    const float* c_convw = (const float*)d_in[13];
    const float* c_convb = (const float*)d_in[14];
    const float* c_dtb   = (const float*)d_in[15];
    const float* c_Alog  = (const float*)d_in[16];
    const float* c_D     = (const float*)d_in[17];
    const float* c_normw = (const float*)d_in[18];
    const float* c_Wout  = (const float*)d_in[19];
    const float* outp_w  = (const float*)d_in[20];
    const float* outp_b  = (const float*)d_in[21];
    float* out = (float*)d_out;

    float *uP32, *zxP, *nrmP, *fsP, *win32P, *wout32P, *wo32P;
    cudaGetSymbolAddress((void**)&uP32,   g_u32);
    cudaGetSymbolAddress((void**)&zxP,    g_zx);
    cudaGetSymbolAddress((void**)&nrmP,   g_nrm);
    cudaGetSymbolAddress((void**)&fsP,    g_fs);
    cudaGetSymbolAddress((void**)&win32P, g_win32);
    cudaGetSymbolAddress((void**)&wout32P,g_wout32);
    cudaGetSymbolAddress((void**)&wo32P,  g_wo32);

    cudaFuncSetAttribute(gemm_tf32, cudaFuncAttributeMaxDynamicSharedMemorySize, GEMM_SMEM);

    float* u32_f = uP32;
    float* u32_c = uP32 + BB * LL * DM;
    float* zx_f = zxP;
    float* zx_c = zxP + BB * LL * ZXW;
    float* nrm_f = nrmP;
    float* nrm_c = nrmP + BB * LQ * DIN;
    float* win_f = win32P;
    float* win_c = win32P + DM * ZXW;
    float* wout_f = wout32P;
    float* wout_c = wout32P + DIN * DM;

    // (0) input rmsnorm
    prep_norm<<<2 * BB * LL, 128>>>(query, kv, fnorm_w, cnorm_w);

    // (1) dt columns + softplus + dA (fp32, both branches)
    {
        dim3 grid((BB * LL) / 16, 2);
        dt_gemm<<<grid, 256>>>(f_Win, c_Win, f_dtb, c_dtb, f_Alog, c_Alog);
    }

    // (2) weight conversions (single launch)
    {
        dim3 grid((DM * ZXW + 255) / 256, 5);
        cvt_all<<<grid, 256>>>(f_Win, c_Win, f_Wout, c_Wout, outp_w);
    }

    // (3) in_proj GEMMs: (8192 x 512) @ (512 x 2176)
    {
        dim3 grid(ZXW / 128, (BB * LL) / 256, 2);
        gemm_tf32<<<grid, 256, GEMM_SMEM>>>(u32_f, u32_c, win_f, win_c, zx_f, zx_c,
                                            nullptr, BB * LL, ZXW, DM, DM, ZXW, ZXW, 0);
    }

    // (4) conv + silu (both branches)
    {
        dim3 grid(BB * LL, 2);
        conv_silu<<<grid, 288>>>(f_convw, f_convb, c_convw, c_convb);
    }

    // (5) sequential scan, both branches
    scan_kernel<<<128, 512>>>(f_D, c_D);

    // (6) gate + rmsnorm (only the output slice)
    yz_norm<<<2 * BB * LQ, 256>>>(f_normw, c_normw);

    // (7) out-projection GEMMs: (4096 x 1024) @ (1024 x 512)
    {
        dim3 grid(DM / 128, (BB * LQ) / 256, 2);
        gemm_tf32<<<grid, 256, GEMM_SMEM>>>(nrm_f, nrm_c, wout_f, wout_c,
                                            fsP, out + BB * LQ * DM,
                                            nullptr, BB * LQ, DM, DIN, DIN, DM, DM, 1);
    }

    // (8) factual final projection with bias: (4096 x 512) @ (512 x 512) + b
    {
        dim3 grid(DM / 128, (BB * LQ) / 256, 1);
        gemm_tf32<<<grid, 256, GEMM_SMEM>>>(fsP, fsP, wo32P, wo32P, out, out,
                                            outp_b, BB * LQ, DM, DM, DM, DM, DM, 0);
    }
}

// round 9
// speedup vs baseline: 1.1727x; 1.1727x over previous
#include <cuda_runtime.h>
#include <math.h>
#include <stdint.h>

#define BB 4
#define LL 2048
#define LQ 1024
#define DM 512
#define DIN 1024
#define DSTATE 64
#define NH 16
#define HD 64
#define DXBC 1152
#define ZXW 2176      // z + xBC columns kept in g_zx (row stride)
#define WIN_LD 2192   // full in_proj width (z + xBC + dt)

// ---------------- scratch (device globals; allocation-free) ----------------
__device__ float g_u[2][BB*LL*DM];        // rmsnormed inputs (fp32, for dt path)
__device__ float g_u32[2][BB*LL*DM];      // rmsnormed inputs (tf32-rounded, GEMM A)
__device__ float g_zx[2][BB*LL*ZXW];      // in_proj outputs (z + xBC)
__device__ float g_xbc[2][BB*LL*DXBC];    // conv+silu outputs
__device__ float g_dt[2][BB*LL*NH];
__device__ float g_dA[2][BB*LL*NH];
__device__ float g_y[2][BB*LL*DIN];       // scan outputs (+D*x)
__device__ float g_nrm[2][BB*LQ*DIN];     // gated rmsnorm (tf32-rounded)
__device__ float g_fs[BB*LQ*DM];          // factual pre-out-proj (tf32-rounded)
__device__ float g_win32[2][DM*ZXW];      // tf32 weights
__device__ float g_wout32[2][DIN*DM];
__device__ float g_wo32[DM*DM];

// ---------------- helpers ----------------
__device__ __forceinline__ float silu(float x) { return x / (1.f + expf(-x)); }

__device__ __forceinline__ uint32_t f2tf32(float x) {
    uint32_t r;
    asm("cvt.rna.tf32.f32 %0, %1;" : "=r"(r) : "f"(x));
    return r;
}
__device__ __forceinline__ float tf32r(float x) { return __uint_as_float(f2tf32(x)); }

__device__ __forceinline__ void mma_tf32(float* c, const uint32_t* a, const uint32_t* b) {
    asm volatile("mma.sync.aligned.m16n8k8.row.col.f32.tf32.tf32.f32 "
        "{%0,%1,%2,%3}, {%4,%5,%6,%7}, {%8,%9}, {%0,%1,%2,%3};"
        : "+f"(c[0]), "+f"(c[1]), "+f"(c[2]), "+f"(c[3])
        : "r"(a[0]), "r"(a[1]), "r"(a[2]), "r"(a[3]), "r"(b[0]), "r"(b[1]));
}

__device__ __forceinline__ void cpa16(float* dst, const float* src) {
    uint32_t d = (uint32_t)__cvta_generic_to_shared(dst);
    asm volatile("cp.async.cg.shared.global [%0], [%1], 16;" :: "r"(d), "l"(src));
}
__device__ __forceinline__ void cpa_commit() { asm volatile("cp.async.commit_group;"); }
template<int N> __device__ __forceinline__ void cpa_wait() {
    asm volatile("cp.async.wait_group %0;" :: "n"(N));
}

// ---------------- 1) input rmsnorm (concat + optional flip) ----------------
__global__ void prep_norm(const float* __restrict__ q, const float* __restrict__ kv,
                          const float* __restrict__ fw, const float* __restrict__ cw)
{
    int row = blockIdx.x;            // 2 * 4 * 2048 rows
    int br  = row >> 13;
    int r   = row & 8191;
    int b   = r >> 11;
    int l   = r & 2047;
    const float* src;
    if (l < LQ) {
        int li = (br == 0) ? l : (LQ - 1 - l);
        src = kv + (b * LQ + li) * DM;
    } else {
        src = q + (b * LQ + (l - LQ)) * DM;
    }
    const float* w = br ? cw : fw;

    int t = threadIdx.x;             // 128
    float v[4];
    float ss = 0.f;
#pragma unroll
    for (int i = 0; i < 4; i++) { v[i] = src[t + i * 128]; ss += v[i] * v[i]; }

    __shared__ float red[4];
#pragma unroll
    for (int o = 16; o > 0; o >>= 1) ss += __shfl_xor_sync(0xffffffffu, ss, o);
    if ((t & 31) == 0) red[t >> 5] = ss;
    __syncthreads();
    float total = red[0] + red[1] + red[2] + red[3];
    float scale = rsqrtf(total / (float)DM + 1e-5f);

    float* dst   = g_u[br]   + (b * LL + l) * DM;
    float* dst32 = g_u32[br] + (b * LL + l) * DM;
#pragma unroll
    for (int i = 0; i < 4; i++) {
        int idx = t + i * 128;
        float val = v[i] * scale * w[idx];
        dst[idx] = val;
        dst32[idx] = tf32r(val);
    }
}

// ---------------- dt GEMM (fp32) + softplus + dA (both branches) -----------
__global__ void __launch_bounds__(256) dt_gemm(
    const float* __restrict__ fWin, const float* __restrict__ cWin,
    const float* __restrict__ fdtb, const float* __restrict__ cdtb,
    const float* __restrict__ fAl,  const float* __restrict__ cAl)
{
    int br = blockIdx.y;
    const float* Win = br ? cWin : fWin;
    const float* dtb = br ? cdtb : fdtb;
    const float* Alog = br ? cAl : fAl;
    const float* u = g_u[br];

    __shared__ float Ws[512][16];
    int tid = threadIdx.x;
    for (int i = tid; i < 512 * 16; i += 256) {
        int k = i >> 4, h = i & 15;
        Ws[k][h] = Win[k * WIN_LD + ZXW + h];
    }
    __syncthreads();

    int rib = tid >> 4;
    int h   = tid & 15;
    int row = blockIdx.x * 16 + rib;
    const float* arow = u + row * DM;

    float a0 = 0.f, a1 = 0.f, a2 = 0.f, a3 = 0.f;
#pragma unroll 4
    for (int k = 0; k < 512; k += 4) {
        a0 += arow[k]     * Ws[k][h];
        a1 += arow[k + 1] * Ws[k + 1][h];
        a2 += arow[k + 2] * Ws[k + 2][h];
        a3 += arow[k + 3] * Ws[k + 3][h];
    }
    float acc = dtb[h] + ((a0 + a1) + (a2 + a3));

    float dt = acc > 20.f ? acc : log1pf(expf(acc));
    int idx = row * NH + h;
    g_dt[br][idx] = dt;
    g_dA[br][idx] = expf(-expf(Alog[h]) * dt);
}

// ---------------- weight tf32 conversion (single launch, 5 regions) --------
__global__ void cvt_all(const float* __restrict__ fWin, const float* __restrict__ cWin,
                        const float* __restrict__ fWout, const float* __restrict__ cWout,
                        const float* __restrict__ oW)
{
    int reg = blockIdx.y;
    int i = blockIdx.x * 256 + threadIdx.x;
    if (reg < 2) {
        if (i >= DM * ZXW) return;
        const float* s = reg ? cWin : fWin;
        float* d = g_win32[reg];
        int r = i / ZXW, c = i - r * ZXW;
        d[i] = tf32r(s[r * WIN_LD + c]);
    } else if (reg < 4) {
        if (i >= DIN * DM) return;
        const float* s = (reg == 2) ? fWout : cWout;
        g_wout32[reg - 2][i] = tf32r(s[i]);
    } else {
        if (i >= DM * DM) return;
        g_wo32[i] = tf32r(oW[i]);
    }
}

// ---------------- TF32 GEMM: 128x128x32 tile, 8 warps (64x32), 3-stage -----
// (R7-proven config: 107.5 KB smem -> 2 CTAs/SM)
#define AS_LD 36
#define BS_LD 136
#define A_STG (128 * AS_LD)    // 4608 floats
#define B_STG (32 * BS_LD)     // 4352 floats
#define B_OFF (3 * A_STG)
#define GEMM_SMEM ((3 * (A_STG + B_STG)) * 4)

__global__ void __launch_bounds__(256) gemm_tf32(
    const float* __restrict__ A0, const float* __restrict__ A1,
    const float* __restrict__ B0, const float* __restrict__ B1,
    float* __restrict__ C0, float* __restrict__ C1,
    const float* __restrict__ bias,
    int M, int N, int K, int lda, int ldb, int ldc, int roundMask)
{
    extern __shared__ float sm[];
    int z = blockIdx.z;
    const float* A = z ? A1 : A0;
    const float* B = z ? B1 : B0;
    float* C = z ? C1 : C0;
    bool rnd = (roundMask >> z) & 1;

    int tid = threadIdx.x;
    int bm = blockIdx.y * 128, bn = blockIdx.x * 128;

    int w = tid >> 5;
    int lane = tid & 31;
    int g = lane >> 2, cq = lane & 3;
    int mw = (w & 1) * 64;
    int nw = (w >> 1) * 32;

    int a_r = tid >> 3, a_c4 = (tid & 7) * 4;
    int b_r = tid >> 5, b_c4 = (tid & 31) * 4;

    const float* Ag = A + (bm + a_r) * lda + a_c4;
    const float* Bg = B + b_r * ldb + bn + b_c4;

    int nk = K >> 5;

    // prologue: prefetch stages 0,1
#pragma unroll
    for (int st = 0; st < 2; st++) {
        float* As = sm + st * A_STG;
        float* Bs = sm + B_OFF + st * B_STG;
#pragma unroll
        for (int rr = 0; rr < 4; rr++)
            cpa16(&As[(a_r + rr * 32) * AS_LD + a_c4], Ag + rr * 32 * lda + st * 32);
#pragma unroll
        for (int rr = 0; rr < 4; rr++)
            cpa16(&Bs[(b_r + rr * 8) * BS_LD + b_c4], Bg + (st * 32 + rr * 8) * ldb);
        cpa_commit();
    }

    float acc[4][4][4];
#pragma unroll
    for (int i = 0; i < 4; i++)
#pragma unroll
        for (int j = 0; j < 4; j++)
#pragma unroll
            for (int x = 0; x < 4; x++) acc[i][j][x] = 0.f;

    for (int kt = 0; kt < nk; kt++) {
        if (kt + 1 < nk) cpa_wait<1>(); else cpa_wait<0>();
        __syncthreads();

        if (kt + 2 < nk) {
            int st = (kt + 2) % 3;
            float* As = sm + st * A_STG;
            float* Bs = sm + B_OFF + st * B_STG;
            int k0 = (kt + 2) * 32;
#pragma unroll
            for (int rr = 0; rr < 4; rr++)
                cpa16(&As[(a_r + rr * 32) * AS_LD + a_c4], Ag + rr * 32 * lda + k0);
#pragma unroll
            for (int rr = 0; rr < 4; rr++)
                cpa16(&Bs[(b_r + rr * 8) * BS_LD + b_c4], Bg + (k0 + rr * 8) * ldb);
            cpa_commit();
        }

        const float* As = sm + (kt % 3) * A_STG;
        const float* Bs = sm + B_OFF + (kt % 3) * B_STG;
#pragma unroll
        for (int ks = 0; ks < 4; ks++) {
            int k0 = ks * 8;
            uint32_t af[4][4], bf[4][2];
#pragma unroll
            for (int i = 0; i < 4; i++) {
                int m = mw + i * 16 + g;
                af[i][0] = __float_as_uint(As[m * AS_LD + k0 + cq]);
                af[i][1] = __float_as_uint(As[(m + 8) * AS_LD + k0 + cq]);
                af[i][2] = __float_as_uint(As[m * AS_LD + k0 + cq + 4]);
                af[i][3] = __float_as_uint(As[(m + 8) * AS_LD + k0 + cq + 4]);
            }
#pragma unroll
            for (int j = 0; j < 4; j++) {
                int n = nw + j * 8 + g;
                bf[j][0] = __float_as_uint(Bs[(k0 + cq) * BS_LD + n]);
                bf[j][1] = __float_as_uint(Bs[(k0 + cq + 4) * BS_LD + n]);
            }
#pragma unroll
            for (int i = 0; i < 4; i++)
#pragma unroll
                for (int j = 0; j < 4; j++)
                    mma_tf32(acc[i][j], af[i], bf[j]);
        }
    }

    // epilogue
#pragma unroll
    for (int i = 0; i < 4; i++) {
        int m0 = bm + mw + i * 16 + g;
#pragma unroll
        for (int j = 0; j < 4; j++) {
            int n = bn + nw + j * 8 + 2 * cq;
            float b0 = 0.f, b1 = 0.f;
            if (bias) { b0 = bias[n]; b1 = bias[n + 1]; }
            float v00 = acc[i][j][0] + b0, v01 = acc[i][j][1] + b1;
            float v10 = acc[i][j][2] + b0, v11 = acc[i][j][3] + b1;
            if (rnd) { v00 = tf32r(v00); v01 = tf32r(v01); v10 = tf32r(v10); v11 = tf32r(v11); }
            float2 lo = { v00, v01 }, hi = { v10, v11 };
            *(float2*)&C[m0 * ldc + n] = lo;
            *(float2*)&C[(m0 + 8) * ldc + n] = hi;
        }
    }
}

// ---------------- causal depthwise conv + silu (vectorized, no div) --------
__global__ void __launch_bounds__(288) conv_silu(
    const float* __restrict__ fw, const float* __restrict__ fb,
    const float* __restrict__ cw_, const float* __restrict__ cb)
{
    int br = blockIdx.y;
    const float* w = br ? cw_ : fw;
    const float* bias = br ? cb : fb;
    int row = blockIdx.x;            // BB * LL
    int b = row >> 11;
    int l = row & 2047;
    int c4 = threadIdx.x * 4;        // 288 threads * 4 ch = 1152

    float4 w0 = *(const float4*)(w + c4 * 4);
    float4 w1 = *(const float4*)(w + c4 * 4 + 4);
    float4 w2 = *(const float4*)(w + c4 * 4 + 8);
    float4 w3 = *(const float4*)(w + c4 * 4 + 12);
    float4 acc = *(const float4*)(bias + c4);

    const float* zbase = g_zx[br] + (size_t)(b * LL) * ZXW + DIN + c4;
#pragma unroll
    for (int j = 0; j < 4; j++) {
        int ls = l - 3 + j;
        if (ls >= 0) {
            float4 x = *(const float4*)(zbase + (size_t)ls * ZXW);
            acc.x += x.x * ((const float*)&w0)[j];
            acc.y += x.y * ((const float*)&w1)[j];
            acc.z += x.z * ((const float*)&w2)[j];
            acc.w += x.w * ((const float*)&w3)[j];
        }
    }
    float4 outv = { silu(acc.x), silu(acc.y), silu(acc.z), silu(acc.w) };
    *(float4*)(g_xbc[br] + (size_t)row * DXBC + c4) = outv;
}

// ---------------- SSD sequential scan, 8-step chunks, batched shfl ---------
#define CHS 8
__global__ void __launch_bounds__(512) scan_kernel(const float* __restrict__ fD,
                                                   const float* __restrict__ cD)
{
    int blk = blockIdx.x;            // 128 = 2 * 4 * 16
    int br = blk >> 6;
    int r = blk & 63;
    int b = r >> 4;
    int h = r & 15;
    const float* xbc = g_xbc[br];
    const float* dtp = g_dt[br];
    const float* dAp = g_dA[br];
    const float* Dp  = br ? cD : fD;
    float* yp = g_y[br];

    __shared__ float xs[2][CHS][64], bs[2][CHS][64], cs_[2][CHS][64], sc[2][CHS][2];

    int t = threadIdx.x;             // 512
    int p = t >> 3;
    int nb = (t & 7) << 3;
    int step = t >> 6, slot = t & 63;
    float Dh = Dp[h];

    float hreg[8];
#pragma unroll
    for (int j = 0; j < 8; j++) hreg[j] = 0.f;

    int rowbase = b * LL;

    float rx, rb, rc, rs = 0.f;
    {
        const float* base = xbc + (rowbase + step) * DXBC;
        rx = base[h * 64 + slot];
        rb = base[1024 + slot];
        rc = base[1088 + slot];
        if (t < 8)       rs = dtp[(rowbase + t) * NH + h];
        else if (t < 16) rs = dAp[(rowbase + (t - 8)) * NH + h];
    }

    int cur = 0;
    for (int c = 0; c < LL / CHS; c++) {
        xs[cur][step][slot]  = rx;
        bs[cur][step][slot]  = rb;
        cs_[cur][step][slot] = rc;
        if (t < 8)       sc[cur][t][0] = rs;
        else if (t < 16) sc[cur][t - 8][1] = rs;
        __syncthreads();

        if (c + 1 < LL / CHS) {
            int l0n = (c + 1) * CHS;
            const float* base = xbc + (rowbase + l0n + step) * DXBC;
            rx = base[h * 64 + slot];
            rb = base[1024 + slot];
            rc = base[1088 + slot];
            if (t < 8)       rs = dtp[(rowbase + l0n + t) * NH + h];
            else if (t < 16) rs = dAp[(rowbase + l0n + (t - 8)) * NH + h];
        }

        float accv[CHS], yv[CHS];
#pragma unroll
        for (int s = 0; s < CHS; s++) {
            float dtv = sc[cur][s][0], dav = sc[cur][s][1];
            float xv = xs[cur][s][p];
            float dtx = dtv * xv;
            float4 b0 = *(const float4*)&bs[cur][s][nb];
            float4 b1 = *(const float4*)&bs[cur][s][nb + 4];
            float4 c0 = *(const float4*)&cs_[cur][s][nb];
            float4 c1 = *(const float4*)&cs_[cur][s][nb + 4];
            float a;
            hreg[0] = hreg[0] * dav + dtx * b0.x; a  = hreg[0] * c0.x;
            hreg[1] = hreg[1] * dav + dtx * b0.y; a += hreg[1] * c0.y;
            hreg[2] = hreg[2] * dav + dtx * b0.z; a += hreg[2] * c0.z;
            hreg[3] = hreg[3] * dav + dtx * b0.w; a += hreg[3] * c0.w;
            hreg[4] = hreg[4] * dav + dtx * b1.x; a += hreg[4] * c1.x;
            hreg[5] = hreg[5] * dav + dtx * b1.y; a += hreg[5] * c1.y;
            hreg[6] = hreg[6] * dav + dtx * b1.z; a += hreg[6] * c1.z;
            hreg[7] = hreg[7] * dav + dtx * b1.w; a += hreg[7] * c1.w;
            accv[s] = a;
            yv[s] = Dh * xv;
        }
#pragma unroll
        for (int s = 0; s < CHS; s++) accv[s] += __shfl_xor_sync(0xffffffffu, accv[s], 1);
#pragma unroll
        for (int s = 0; s < CHS; s++) accv[s] += __shfl_xor_sync(0xffffffffu, accv[s], 2);
#pragma unroll
        for (int s = 0; s < CHS; s++) accv[s] += __shfl_xor_sync(0xffffffffu, accv[s], 4);

        int l0 = c * CHS;
        if ((t & 7) == 0) {
#pragma unroll
            for (int s = 0; s < CHS; s++)
                yp[(rowbase + l0 + s) * DIN + h * HD + p] = accv[s] + yv[s];
        }
        cur ^= 1;
    }
}

// ---------------- y * silu(z) + rmsnorm (last LQ tokens, tf32 out) ---------
__global__ void yz_norm(const float* __restrict__ fnw, const float* __restrict__ cnw)
{
    int row = blockIdx.x;            // 2 * 4 * 1024
    int br = row >> 12;
    int r = row & 4095;
    int b = r >> 10;
    int lq = r & 1023;
    int l = lq + LQ;
    const float* nw = br ? cnw : fnw;
    const float* yrow = g_y[br] + (b * LL + l) * DIN;
    const float* zrow = g_zx[br] + (b * LL + l) * ZXW;

    int t = threadIdx.x;             // 256
    float v[4];
    float ss = 0.f;
#pragma unroll
    for (int i = 0; i < 4; i++) {
        int idx = t + i * 256;
        float z = zrow[idx];
        float val = yrow[idx] * silu(z);
        v[i] = val;
        ss += val * val;
    }

    __shared__ float red[8];
#pragma unroll
    for (int o = 16; o > 0; o >>= 1) ss += __shfl_xor_sync(0xffffffffu, ss, o);
    if ((t & 31) == 0) red[t >> 5] = ss;
    __syncthreads();
    float total = 0.f;
#pragma unroll
    for (int i = 0; i < 8; i++) total += red[i];
    float scale = rsqrtf(total / (float)DIN + 1e-5f);

    float* dst = g_nrm[br] + ((b << 10) + lq) * DIN;
#pragma unroll
    for (int i = 0; i < 4; i++) {
        int idx = t + i * 256;
        dst[idx] = tf32r(v[i] * scale * nw[idx]);
    }
}

// ---------------- launch ----------------------------------------------------
extern "C" void kernel_launch(void* const* d_in, const int* in_sizes, int n_in,
                              void* d_out, int out_size)
{
    const float* query   = (const float*)d_in[0];
    const float* kv      = (const float*)d_in[1];
    const float* fnorm_w = (const float*)d_in[2];
    const float* cnorm_w = (const float*)d_in[3];
    const float* f_Win   = (const float*)d_in[4];
    const float* f_convw = (const float*)d_in[5];
    const float* f_convb = (const float*)d_in[6];
    const float* f_dtb   = (const float*)d_in[7];
    const float* f_Alog  = (const float*)d_in[8];
    const float* f_D     = (const float*)d_in[9];
    const float* f_normw = (const float*)d_in[10];
    const float* f_Wout  = (const float*)d_in[11];
    const float* c_Win   = (const float*)d_in[12];
    const float* c_convw = (const float*)d_in[13];
    const float* c_convb = (const float*)d_in[14];
    const float* c_dtb   = (const float*)d_in[15];
    const float* c_Alog  = (const float*)d_in[16];
    const float* c_D     = (const float*)d_in[17];
    const float* c_normw = (const float*)d_in[18];
    const float* c_Wout  = (const float*)d_in[19];
    const float* outp_w  = (const float*)d_in[20];
    const float* outp_b  = (const float*)d_in[21];
    float* out = (float*)d_out;

    float *uP32, *zxP, *nrmP, *fsP, *win32P, *wout32P, *wo32P;
    cudaGetSymbolAddress((void**)&uP32,   g_u32);
    cudaGetSymbolAddress((void**)&zxP,    g_zx);
    cudaGetSymbolAddress((void**)&nrmP,   g_nrm);
    cudaGetSymbolAddress((void**)&fsP,    g_fs);
    cudaGetSymbolAddress((void**)&win32P, g_win32);
    cudaGetSymbolAddress((void**)&wout32P,g_wout32);
    cudaGetSymbolAddress((void**)&wo32P,  g_wo32);

    cudaFuncSetAttribute(gemm_tf32, cudaFuncAttributeMaxDynamicSharedMemorySize, GEMM_SMEM);

    float* u32_f = uP32;
    float* u32_c = uP32 + BB * LL * DM;
    float* zx_f = zxP;
    float* zx_c = zxP + BB * LL * ZXW;
    float* nrm_f = nrmP;
    float* nrm_c = nrmP + BB * LQ * DIN;
    float* win_f = win32P;
    float* win_c = win32P + DM * ZXW;
    float* wout_f = wout32P;
    float* wout_c = wout32P + DIN * DM;

    // (0) input rmsnorm
    prep_norm<<<2 * BB * LL, 128>>>(query, kv, fnorm_w, cnorm_w);

    // (1) dt columns + softplus + dA (fp32, both branches)
    {
        dim3 grid((BB * LL) / 16, 2);
        dt_gemm<<<grid, 256>>>(f_Win, c_Win, f_dtb, c_dtb, f_Alog, c_Alog);
    }

    // (2) weight conversions (single launch)
    {
        dim3 grid((DM * ZXW + 255) / 256, 5);
        cvt_all<<<grid, 256>>>(f_Win, c_Win, f_Wout, c_Wout, outp_w);
    }

    // (3) in_proj GEMMs: (8192 x 512) @ (512 x 2176)
    {
        dim3 grid(ZXW / 128, (BB * LL) / 128, 2);
        gemm_tf32<<<grid, 256, GEMM_SMEM>>>(u32_f, u32_c, win_f, win_c, zx_f, zx_c,
                                            nullptr, BB * LL, ZXW, DM, DM, ZXW, ZXW, 0);
    }

    // (4) conv + silu (both branches)
    {
        dim3 grid(BB * LL, 2);
        conv_silu<<<grid, 288>>>(f_convw, f_convb, c_convw, c_convb);
    }

    // (5) sequential scan, both branches
    scan_kernel<<<128, 512>>>(f_D, c_D);

    // (6) gate + rmsnorm (only the output slice)
    yz_norm<<<2 * BB * LQ, 256>>>(f_normw, c_normw);

    // (7) out-projection GEMMs: (4096 x 1024) @ (1024 x 512)
    {
        dim3 grid(DM / 128, (BB * LQ) / 128, 2);
        gemm_tf32<<<grid, 256, GEMM_SMEM>>>(nrm_f, nrm_c, wout_f, wout_c,
                                            fsP, out + BB * LQ * DM,
                                            nullptr, BB * LQ, DM, DIN, DIN, DM, DM, 1);
    }

    // (8) factual final projection with bias: (4096 x 512) @ (512 x 512) + b
    {
        dim3 grid(DM / 128, (BB * LQ) / 128, 1);
        gemm_tf32<<<grid, 256, GEMM_SMEM>>>(fsP, fsP, wo32P, wo32P, out, out,
                                            outp_b, BB * LQ, DM, DM, DM, DM, DM, 0);
    }
}

// round 10
// speedup vs baseline: 1.2401x; 1.0575x over previous
#include <cuda_runtime.h>
#include <math.h>
#include <stdint.h>

#define BB 4
#define LL 2048
#define LQ 1024
#define DM 512
#define DIN 1024
#define DSTATE 64
#define NH 16
#define HD 64
#define DXBC 1152
#define ZXW 2176      // z + xBC columns kept in g_zx (row stride)
#define WIN_LD 2192   // full in_proj width (z + xBC + dt)

// ---------------- scratch (device globals; allocation-free) ----------------
__device__ float g_u[2][BB*LL*DM];        // rmsnormed inputs (fp32, for dt path)
__device__ float g_u32[2][BB*LL*DM];      // rmsnormed inputs (tf32-rounded, GEMM A)
__device__ float g_zx[2][BB*LL*ZXW];      // in_proj outputs (z + xBC)
__device__ float g_xbc[2][BB*LL*DXBC];    // conv+silu outputs
__device__ float g_dt[2][BB*LL*NH];
__device__ float g_dA[2][BB*LL*NH];
__device__ float g_y[2][BB*LL*DIN];       // scan outputs (+D*x)
__device__ float g_nrm[2][BB*LQ*DIN];     // gated rmsnorm (tf32-rounded)
__device__ float g_fs[BB*LQ*DM];          // factual pre-out-proj (tf32-rounded)
__device__ float g_win32[2][DM*ZXW];      // tf32 weights
__device__ float g_wout32[2][DIN*DM];
__device__ float g_wo32[DM*DM];

// ---------------- helpers ----------------
__device__ __forceinline__ float silu(float x) { return x / (1.f + expf(-x)); }

__device__ __forceinline__ uint32_t f2tf32(float x) {
    uint32_t r;
    asm("cvt.rna.tf32.f32 %0, %1;" : "=r"(r) : "f"(x));
    return r;
}
__device__ __forceinline__ float tf32r(float x) { return __uint_as_float(f2tf32(x)); }

__device__ __forceinline__ void mma_tf32(float* c, const uint32_t* a, const uint32_t* b) {
    asm volatile("mma.sync.aligned.m16n8k8.row.col.f32.tf32.tf32.f32 "
        "{%0,%1,%2,%3}, {%4,%5,%6,%7}, {%8,%9}, {%0,%1,%2,%3};"
        : "+f"(c[0]), "+f"(c[1]), "+f"(c[2]), "+f"(c[3])
        : "r"(a[0]), "r"(a[1]), "r"(a[2]), "r"(a[3]), "r"(b[0]), "r"(b[1]));
}

__device__ __forceinline__ void cpa16(float* dst, const float* src) {
    uint32_t d = (uint32_t)__cvta_generic_to_shared(dst);
    asm volatile("cp.async.cg.shared.global [%0], [%1], 16;" :: "r"(d), "l"(src));
}
__device__ __forceinline__ void cpa_commit() { asm volatile("cp.async.commit_group;"); }
template<int N> __device__ __forceinline__ void cpa_wait() {
    asm volatile("cp.async.wait_group %0;" :: "n"(N));
}

// ---------------- 1) input rmsnorm (concat + optional flip) ----------------
__global__ void prep_norm(const float* __restrict__ q, const float* __restrict__ kv,
                          const float* __restrict__ fw, const float* __restrict__ cw)
{
    int row = blockIdx.x;            // 2 * 4 * 2048 rows
    int br  = row >> 13;
    int r   = row & 8191;
    int b   = r >> 11;
    int l   = r & 2047;
    const float* src;
    if (l < LQ) {
        int li = (br == 0) ? l : (LQ - 1 - l);
        src = kv + (b * LQ + li) * DM;
    } else {
        src = q + (b * LQ + (l - LQ)) * DM;
    }
    const float* w = br ? cw : fw;

    int t = threadIdx.x;             // 128
    float v[4];
    float ss = 0.f;
#pragma unroll
    for (int i = 0; i < 4; i++) { v[i] = src[t + i * 128]; ss += v[i] * v[i]; }

    __shared__ float red[4];
#pragma unroll
    for (int o = 16; o > 0; o >>= 1) ss += __shfl_xor_sync(0xffffffffu, ss, o);
    if ((t & 31) == 0) red[t >> 5] = ss;
    __syncthreads();
    float total = red[0] + red[1] + red[2] + red[3];
    float scale = rsqrtf(total / (float)DM + 1e-5f);

    float* dst   = g_u[br]   + (b * LL + l) * DM;
    float* dst32 = g_u32[br] + (b * LL + l) * DM;
#pragma unroll
    for (int i = 0; i < 4; i++) {
        int idx = t + i * 128;
        float val = v[i] * scale * w[idx];
        dst[idx] = val;
        dst32[idx] = tf32r(val);
    }
}

// ---------------- dt GEMM (fp32) + softplus + dA (both branches) -----------
__global__ void __launch_bounds__(256) dt_gemm(
    const float* __restrict__ fWin, const float* __restrict__ cWin,
    const float* __restrict__ fdtb, const float* __restrict__ cdtb,
    const float* __restrict__ fAl,  const float* __restrict__ cAl)
{
    int br = blockIdx.y;
    const float* Win = br ? cWin : fWin;
    const float* dtb = br ? cdtb : fdtb;
    const float* Alog = br ? cAl : fAl;
    const float* u = g_u[br];

    __shared__ float Ws[512][16];
    int tid = threadIdx.x;
    for (int i = tid; i < 512 * 16; i += 256) {
        int k = i >> 4, h = i & 15;
        Ws[k][h] = Win[k * WIN_LD + ZXW + h];
    }
    __syncthreads();

    int rib = tid >> 4;
    int h   = tid & 15;
    int row = blockIdx.x * 16 + rib;
    const float* arow = u + row * DM;

    float a0 = 0.f, a1 = 0.f, a2 = 0.f, a3 = 0.f;
#pragma unroll 4
    for (int k = 0; k < 512; k += 4) {
        a0 += arow[k]     * Ws[k][h];
        a1 += arow[k + 1] * Ws[k + 1][h];
        a2 += arow[k + 2] * Ws[k + 2][h];
        a3 += arow[k + 3] * Ws[k + 3][h];
    }
    float acc = dtb[h] + ((a0 + a1) + (a2 + a3));

    float dt = acc > 20.f ? acc : log1pf(expf(acc));
    int idx = row * NH + h;
    g_dt[br][idx] = dt;
    g_dA[br][idx] = expf(-expf(Alog[h]) * dt);
}

// ---------------- weight tf32 conversion (single launch, 5 regions) --------
__global__ void cvt_all(const float* __restrict__ fWin, const float* __restrict__ cWin,
                        const float* __restrict__ fWout, const float* __restrict__ cWout,
                        const float* __restrict__ oW)
{
    int reg = blockIdx.y;
    int i = blockIdx.x * 256 + threadIdx.x;
    if (reg < 2) {
        if (i >= DM * ZXW) return;
        const float* s = reg ? cWin : fWin;
        float* d = g_win32[reg];
        int r = i / ZXW, c = i - r * ZXW;
        d[i] = tf32r(s[r * WIN_LD + c]);
    } else if (reg < 4) {
        if (i >= DIN * DM) return;
        const float* s = (reg == 2) ? fWout : cWout;
        g_wout32[reg - 2][i] = tf32r(s[i]);
    } else {
        if (i >= DM * DM) return;
        g_wo32[i] = tf32r(oW[i]);
    }
}

// ---------------- TF32 GEMM: 128x128x32 tile, 8 warps (64x32), 3-stage -----
#define AS_LD 36
#define BS_LD 136
#define A_STG (128 * AS_LD)    // 4608 floats
#define B_STG (32 * BS_LD)     // 4352 floats
#define B_OFF (3 * A_STG)
#define GEMM_SMEM ((3 * (A_STG + B_STG)) * 4)

__global__ void __launch_bounds__(256) gemm_tf32(
    const float* __restrict__ A0, const float* __restrict__ A1,
    const float* __restrict__ B0, const float* __restrict__ B1,
    float* __restrict__ C0, float* __restrict__ C1,
    const float* __restrict__ bias,
    int M, int N, int K, int lda, int ldb, int ldc, int roundMask)
{
    extern __shared__ float sm[];
    int z = blockIdx.z;
    const float* A = z ? A1 : A0;
    const float* B = z ? B1 : B0;
    float* C = z ? C1 : C0;
    bool rnd = (roundMask >> z) & 1;

    int tid = threadIdx.x;
    int bm = blockIdx.y * 128, bn = blockIdx.x * 128;

    int w = tid >> 5;
    int lane = tid & 31;
    int g = lane >> 2, cq = lane & 3;
    int mw = (w & 1) * 64;
    int nw = (w >> 1) * 32;

    int a_r = tid >> 3, a_c4 = (tid & 7) * 4;
    int b_r = tid >> 5, b_c4 = (tid & 31) * 4;

    const float* Ag = A + (bm + a_r) * lda + a_c4;
    const float* Bg = B + b_r * ldb + bn + b_c4;

    int nk = K >> 5;

#pragma unroll
    for (int st = 0; st < 2; st++) {
        float* As = sm + st * A_STG;
        float* Bs = sm + B_OFF + st * B_STG;
#pragma unroll
        for (int rr = 0; rr < 4; rr++)
            cpa16(&As[(a_r + rr * 32) * AS_LD + a_c4], Ag + rr * 32 * lda + st * 32);
#pragma unroll
        for (int rr = 0; rr < 4; rr++)
            cpa16(&Bs[(b_r + rr * 8) * BS_LD + b_c4], Bg + (st * 32 + rr * 8) * ldb);
        cpa_commit();
    }

    float acc[4][4][4];
#pragma unroll
    for (int i = 0; i < 4; i++)
#pragma unroll
        for (int j = 0; j < 4; j++)
#pragma unroll
            for (int x = 0; x < 4; x++) acc[i][j][x] = 0.f;

    for (int kt = 0; kt < nk; kt++) {
        if (kt + 1 < nk) cpa_wait<1>(); else cpa_wait<0>();
        __syncthreads();

        if (kt + 2 < nk) {
            int st = (kt + 2) % 3;
            float* As = sm + st * A_STG;
            float* Bs = sm + B_OFF + st * B_STG;
            int k0 = (kt + 2) * 32;
#pragma unroll
            for (int rr = 0; rr < 4; rr++)
                cpa16(&As[(a_r + rr * 32) * AS_LD + a_c4], Ag + rr * 32 * lda + k0);
#pragma unroll
            for (int rr = 0; rr < 4; rr++)
                cpa16(&Bs[(b_r + rr * 8) * BS_LD + b_c4], Bg + (k0 + rr * 8) * ldb);
            cpa_commit();
        }

        const float* As = sm + (kt % 3) * A_STG;
        const float* Bs = sm + B_OFF + (kt % 3) * B_STG;
#pragma unroll
        for (int ks = 0; ks < 4; ks++) {
            int k0 = ks * 8;
            uint32_t af[4][4], bf[4][2];
#pragma unroll
            for (int i = 0; i < 4; i++) {
                int m = mw + i * 16 + g;
                af[i][0] = __float_as_uint(As[m * AS_LD + k0 + cq]);
                af[i][1] = __float_as_uint(As[(m + 8) * AS_LD + k0 + cq]);
                af[i][2] = __float_as_uint(As[m * AS_LD + k0 + cq + 4]);
                af[i][3] = __float_as_uint(As[(m + 8) * AS_LD + k0 + cq + 4]);
            }
#pragma unroll
            for (int j = 0; j < 4; j++) {
                int n = nw + j * 8 + g;
                bf[j][0] = __float_as_uint(Bs[(k0 + cq) * BS_LD + n]);
                bf[j][1] = __float_as_uint(Bs[(k0 + cq + 4) * BS_LD + n]);
            }
#pragma unroll
            for (int i = 0; i < 4; i++)
#pragma unroll
                for (int j = 0; j < 4; j++)
                    mma_tf32(acc[i][j], af[i], bf[j]);
        }
    }

#pragma unroll
    for (int i = 0; i < 4; i++) {
        int m0 = bm + mw + i * 16 + g;
#pragma unroll
        for (int j = 0; j < 4; j++) {
            int n = bn + nw + j * 8 + 2 * cq;
            float b0 = 0.f, b1 = 0.f;
            if (bias) { b0 = bias[n]; b1 = bias[n + 1]; }
            float v00 = acc[i][j][0] + b0, v01 = acc[i][j][1] + b1;
            float v10 = acc[i][j][2] + b0, v11 = acc[i][j][3] + b1;
            if (rnd) { v00 = tf32r(v00); v01 = tf32r(v01); v10 = tf32r(v10); v11 = tf32r(v11); }
            float2 lo = { v00, v01 }, hi = { v10, v11 };
            *(float2*)&C[m0 * ldc + n] = lo;
            *(float2*)&C[(m0 + 8) * ldc + n] = hi;
        }
    }
}

// ---------------- causal depthwise conv + silu (vectorized, no div) --------
__global__ void __launch_bounds__(288) conv_silu(
    const float* __restrict__ fw, const float* __restrict__ fb,
    const float* __restrict__ cw_, const float* __restrict__ cb)
{
    int br = blockIdx.y;
    const float* w = br ? cw_ : fw;
    const float* bias = br ? cb : fb;
    int row = blockIdx.x;            // BB * LL
    int b = row >> 11;
    int l = row & 2047;
    int c4 = threadIdx.x * 4;        // 288 threads * 4 ch = 1152

    float4 w0 = *(const float4*)(w + c4 * 4);
    float4 w1 = *(const float4*)(w + c4 * 4 + 4);
    float4 w2 = *(const float4*)(w + c4 * 4 + 8);
    float4 w3 = *(const float4*)(w + c4 * 4 + 12);
    float4 acc = *(const float4*)(bias + c4);

    const float* zbase = g_zx[br] + (size_t)(b * LL) * ZXW + DIN + c4;
#pragma unroll
    for (int j = 0; j < 4; j++) {
        int ls = l - 3 + j;
        if (ls >= 0) {
            float4 x = *(const float4*)(zbase + (size_t)ls * ZXW);
            acc.x += x.x * ((const float*)&w0)[j];
            acc.y += x.y * ((const float*)&w1)[j];
            acc.z += x.z * ((const float*)&w2)[j];
            acc.w += x.w * ((const float*)&w3)[j];
        }
    }
    float4 outv = { silu(acc.x), silu(acc.y), silu(acc.z), silu(acc.w) };
    *(float4*)(g_xbc[br] + (size_t)row * DXBC + c4) = outv;
}

// ---------------- SSD scan: register-resident, warp-autonomous -------------
// block = one head (128 threads, 4 warps); warp = 16 p-rows; thread = 4p x 8n.
// depth-4 register prefetch pipeline; no shared memory, no __syncthreads.
__global__ void __launch_bounds__(128) scan_kernel(const float* __restrict__ fD,
                                                   const float* __restrict__ cD)
{
    int blk = blockIdx.x;            // 128 = 2 * 4 * 16
    int br = blk >> 6;
    int r = blk & 63;
    int b = r >> 4;
    int h = r & 15;
    const float* xbc = g_xbc[br];
    const float* dtp = g_dt[br];
    const float* dAp = g_dA[br];
    float Dh = (br ? cD : fD)[h];
    float* yp = g_y[br];

    int w = threadIdx.x >> 5;
    int lane = threadIdx.x & 31;
    int p_sub = lane >> 3, ng = lane & 7;
    int p0 = w * 16 + p_sub * 4;     // 4 p's: p0..p0+3
    int n0 = ng * 8;                 // 8 n's

    const size_t rowbase = (size_t)b * LL;
    const float* xptr = xbc + h * 64 + p0;
    const float* bptr = xbc + 1024 + n0;
    const float* cptr = xbc + 1088 + n0;

    float4 X[4], Bl[4], Bh[4], Cl[4], Ch[4];
    float DT[4], DA[4];

#define SCAN_LOAD(s, l) do { \
        size_t off = (rowbase + (l)) * DXBC; \
        X[s]  = *(const float4*)(xptr + off); \
        Bl[s] = *(const float4*)(bptr + off); \
        Bh[s] = *(const float4*)(bptr + off + 4); \
        Cl[s] = *(const float4*)(cptr + off); \
        Ch[s] = *(const float4*)(cptr + off + 4); \
        int rowi = (int)(rowbase + (l)); \
        DT[s] = dtp[rowi * NH + h]; \
        DA[s] = dAp[rowi * NH + h]; \
    } while (0)

#pragma unroll
    for (int s = 0; s < 4; s++) SCAN_LOAD(s, s);

    float hs[4][8];
#pragma unroll
    for (int j = 0; j < 4; j++)
#pragma unroll
        for (int k = 0; k < 8; k++) hs[j][k] = 0.f;

    for (int l = 0; l < LL; l += 4) {
#pragma unroll
        for (int s = 0; s < 4; s++) {
            float dtv = DT[s], dav = DA[s];
            float4 xv = X[s];
            float4 b0 = Bl[s], b1 = Bh[s], c0 = Cl[s], c1 = Ch[s];
            if (l + s + 4 < LL) SCAN_LOAD(s, l + s + 4);

            float accv[4];
#pragma unroll
            for (int j = 0; j < 4; j++) {
                float xj = ((const float*)&xv)[j];
                float dtx = dtv * xj;
                float* hj = hs[j];
                float a;
                hj[0] = hj[0] * dav + dtx * b0.x; a  = hj[0] * c0.x;
                hj[1] = hj[1] * dav + dtx * b0.y; a += hj[1] * c0.y;
                hj[2] = hj[2] * dav + dtx * b0.z; a += hj[2] * c0.z;
                hj[3] = hj[3] * dav + dtx * b0.w; a += hj[3] * c0.w;
                hj[4] = hj[4] * dav + dtx * b1.x; a += hj[4] * c1.x;
                hj[5] = hj[5] * dav + dtx * b1.y; a += hj[5] * c1.y;
                hj[6] = hj[6] * dav + dtx * b1.z; a += hj[6] * c1.z;
                hj[7] = hj[7] * dav + dtx * b1.w; a += hj[7] * c1.w;
                accv[j] = a;
            }
#pragma unroll
            for (int j = 0; j < 4; j++) accv[j] += __shfl_xor_sync(0xffffffffu, accv[j], 1);
#pragma unroll
            for (int j = 0; j < 4; j++) accv[j] += __shfl_xor_sync(0xffffffffu, accv[j], 2);
#pragma unroll
            for (int j = 0; j < 4; j++) accv[j] += __shfl_xor_sync(0xffffffffu, accv[j], 4);

            if (ng == 0) {
                float4 o = { accv[0] + Dh * xv.x, accv[1] + Dh * xv.y,
                             accv[2] + Dh * xv.z, accv[3] + Dh * xv.w };
                *(float4*)(yp + (rowbase + l + s) * DIN + h * HD + p0) = o;
            }
        }
    }
#undef SCAN_LOAD
}

// ---------------- y * silu(z) + rmsnorm (last LQ tokens, tf32 out) ---------
__global__ void yz_norm(const float* __restrict__ fnw, const float* __restrict__ cnw)
{
    int row = blockIdx.x;            // 2 * 4 * 1024
    int br = row >> 12;
    int r = row & 4095;
    int b = r >> 10;
    int lq = r & 1023;
    int l = lq + LQ;
    const float* nw = br ? cnw : fnw;
    const float* yrow = g_y[br] + (b * LL + l) * DIN;
    const float* zrow = g_zx[br] + (b * LL + l) * ZXW;

    int t = threadIdx.x;             // 256
    float v[4];
    float ss = 0.f;
#pragma unroll
    for (int i = 0; i < 4; i++) {
        int idx = t + i * 256;
        float z = zrow[idx];
        float val = yrow[idx] * silu(z);
        v[i] = val;
        ss += val * val;
    }

    __shared__ float red[8];
#pragma unroll
    for (int o = 16; o > 0; o >>= 1) ss += __shfl_xor_sync(0xffffffffu, ss, o);
    if ((t & 31) == 0) red[t >> 5] = ss;
    __syncthreads();
    float total = 0.f;
#pragma unroll
    for (int i = 0; i < 8; i++) total += red[i];
    float scale = rsqrtf(total / (float)DIN + 1e-5f);

    float* dst = g_nrm[br] + ((b << 10) + lq) * DIN;
#pragma unroll
    for (int i = 0; i < 4; i++) {
        int idx = t + i * 256;
        dst[idx] = tf32r(v[i] * scale * nw[idx]);
    }
}

// ---------------- launch ----------------------------------------------------
extern "C" void kernel_launch(void* const* d_in, const int* in_sizes, int n_in,
                              void* d_out, int out_size)
{
    const float* query   = (const float*)d_in[0];
    const float* kv      = (const float*)d_in[1];
    const float* fnorm_w = (const float*)d_in[2];
    const float* cnorm_w = (const float*)d_in[3];
    const float* f_Win   = (const float*)d_in[4];
    const float* f_convw = (const float*)d_in[5];
    const float* f_convb = (const float*)d_in[6];
    const float* f_dtb   = (const float*)d_in[7];
    const float* f_Alog  = (const float*)d_in[8];
    const float* f_D     = (const float*)d_in[9];
    const float* f_normw = (const float*)d_in[10];
    const float* f_Wout  = (const float*)d_in[11];
    const float* c_Win   = (const float*)d_in[12];
    const float* c_convw = (const float*)d_in[13];
    const float* c_convb = (const float*)d_in[14];
    const float* c_dtb   = (const float*)d_in[15];
    const float* c_Alog  = (const float*)d_in[16];
    const float* c_D     = (const float*)d_in[17];
    const float* c_normw = (const float*)d_in[18];
    const float* c_Wout  = (const float*)d_in[19];
    const float* outp_w  = (const float*)d_in[20];
    const float* outp_b  = (const float*)d_in[21];
    float* out = (float*)d_out;

    float *uP32, *zxP, *nrmP, *fsP, *win32P, *wout32P, *wo32P;
    cudaGetSymbolAddress((void**)&uP32,   g_u32);
    cudaGetSymbolAddress((void**)&zxP,    g_zx);
    cudaGetSymbolAddress((void**)&nrmP,   g_nrm);
    cudaGetSymbolAddress((void**)&fsP,    g_fs);
    cudaGetSymbolAddress((void**)&win32P, g_win32);
    cudaGetSymbolAddress((void**)&wout32P,g_wout32);
    cudaGetSymbolAddress((void**)&wo32P,  g_wo32);

    cudaFuncSetAttribute(gemm_tf32, cudaFuncAttributeMaxDynamicSharedMemorySize, GEMM_SMEM);

    float* u32_f = uP32;
    float* u32_c = uP32 + BB * LL * DM;
    float* zx_f = zxP;
    float* zx_c = zxP + BB * LL * ZXW;
    float* nrm_f = nrmP;
    float* nrm_c = nrmP + BB * LQ * DIN;
    float* win_f = win32P;
    float* win_c = win32P + DM * ZXW;
    float* wout_f = wout32P;
    float* wout_c = wout32P + DIN * DM;

    // (0) input rmsnorm
    prep_norm<<<2 * BB * LL, 128>>>(query, kv, fnorm_w, cnorm_w);

    // (1) dt columns + softplus + dA (fp32, both branches)
    {
        dim3 grid((BB * LL) / 16, 2);
        dt_gemm<<<grid, 256>>>(f_Win, c_Win, f_dtb, c_dtb, f_Alog, c_Alog);
    }

    // (2) weight conversions (single launch)
    {
        dim3 grid((DM * ZXW + 255) / 256, 5);
        cvt_all<<<grid, 256>>>(f_Win, c_Win, f_Wout, c_Wout, outp_w);
    }

    // (3) in_proj GEMMs: (8192 x 512) @ (512 x 2176)
    {
        dim3 grid(ZXW / 128, (BB * LL) / 128, 2);
        gemm_tf32<<<grid, 256, GEMM_SMEM>>>(u32_f, u32_c, win_f, win_c, zx_f, zx_c,
                                            nullptr, BB * LL, ZXW, DM, DM, ZXW, ZXW, 0);
    }

    // (4) conv + silu (both branches)
    {
        dim3 grid(BB * LL, 2);
        conv_silu<<<grid, 288>>>(f_convw, f_convb, c_convw, c_convb);
    }

    // (5) register-resident scan, both branches
    scan_kernel<<<128, 128>>>(f_D, c_D);

    // (6) gate + rmsnorm (only the output slice)
    yz_norm<<<2 * BB * LQ, 256>>>(f_normw, c_normw);

    // (7) out-projection GEMMs: (4096 x 1024) @ (1024 x 512)
    {
        dim3 grid(DM / 128, (BB * LQ) / 128, 2);
        gemm_tf32<<<grid, 256, GEMM_SMEM>>>(nrm_f, nrm_c, wout_f, wout_c,
                                            fsP, out + BB * LQ * DM,
                                            nullptr, BB * LQ, DM, DIN, DIN, DM, DM, 1);
    }

    // (8) factual final projection with bias: (4096 x 512) @ (512 x 512) + b
    {
        dim3 grid(DM / 128, (BB * LQ) / 128, 1);
        gemm_tf32<<<grid, 256, GEMM_SMEM>>>(fsP, fsP, wo32P, wo32P, out, out,
                                            outp_b, BB * LQ, DM, DM, DM, DM, DM, 0);
    }
}